// round 4
// baseline (speedup 1.0000x reference)
#include <cuda_runtime.h>
#include <cuda_bf16.h>
#include <math.h>
#include <float.h>

// HierarchyLoss: out = mean_b( lse(logits[b]) - logits[b,label[b]] )
//              + 0.1 * sum_e ||emb[parent[e]] - emb[child[e]]||^2
//
// Inputs (metadata order) — NOTE: JAX default config downcasts int64 -> int32,
// so all index tensors are int32:
//  0: logits    float32 [B, N]      B=128, N=100000
//  1: labels    int32   [B]
//  2: label_emb float32 [N, D]      D=256
//  3: parent_idx int32  [E]         E=N-1
//  4: child_idx  int32  [E]
// Output: float32 scalar.

#define LSE_SPLIT     8
#define FUSED_THREADS 256
#define EDGE_BLOCKS   1184         // 8 per SM (148 SMs)
#define MAX_B         256
#define HIER_W        0.1f

// Scratch (allocation-free rule: __device__ globals)
__device__ float g_lse_m[MAX_B * LSE_SPLIT];
__device__ float g_lse_s[MAX_B * LSE_SPLIT];
__device__ float g_edge_part[EDGE_BLOCKS];

// ---------------------------------------------------------------------------
// Phase A (blocks [0, B*LSE_SPLIT)): per-(row, split) partial online
// logsumexp over logits. float4 streaming loads.
// ---------------------------------------------------------------------------
__device__ __forceinline__ void lse_phase(const float* __restrict__ logits,
                                          int N, int blk)
{
    const int row  = blk / LSE_SPLIT;
    const int part = blk % LSE_SPLIT;
    const int vecN = N >> 2;                          // N % 4 == 0 (100000)
    const int chunk = (vecN + LSE_SPLIT - 1) / LSE_SPLIT;
    const int c0 = part * chunk;
    const int c1 = min(c0 + chunk, vecN);

    const float4* __restrict__ p =
        reinterpret_cast<const float4*>(logits + (size_t)row * N);

    float m = -FLT_MAX;
    float s = 0.0f;
    for (int i = c0 + threadIdx.x; i < c1; i += FUSED_THREADS) {
        float4 v = p[i];
        float mv = fmaxf(fmaxf(v.x, v.y), fmaxf(v.z, v.w));
        if (mv > m) { s *= __expf(m - mv); m = mv; }
        s += __expf(v.x - m) + __expf(v.y - m) +
             __expf(v.z - m) + __expf(v.w - m);
    }

    __shared__ float sm[FUSED_THREADS];
    __shared__ float ss[FUSED_THREADS];
    const int t = threadIdx.x;
    sm[t] = m; ss[t] = s;
    __syncthreads();
    for (int off = FUSED_THREADS / 2; off > 0; off >>= 1) {
        if (t < off) {
            float m2 = sm[t + off], s2 = ss[t + off];
            float m1 = sm[t],       s1 = ss[t];
            float M = fmaxf(m1, m2);
            ss[t] = s1 * __expf(m1 - M) + s2 * __expf(m2 - M);
            sm[t] = M;
        }
        __syncthreads();
    }
    if (t == 0) {
        g_lse_m[blk] = sm[0];
        g_lse_s[blk] = ss[0];
    }
}

// ---------------------------------------------------------------------------
// Phase B (blocks [B*LSE_SPLIT, ...+EDGE_BLOCKS)): edge penalty partials.
// One warp per edge; lane reads 2 float4 from each of parent/child rows
// (D=256 -> 64 float4/row). Next edge's indices are prefetched to hide the
// index->gather dependency. Indices are defensively clamped to [0, N) so a
// dtype misinterpretation surfaces as rel_err, not an illegal access.
// Per-block reduction -> one scratch slot.
// ---------------------------------------------------------------------------
__device__ __forceinline__ void edge_phase(const float* __restrict__ emb,
                                           const int* __restrict__ par,
                                           const int* __restrict__ chi,
                                           int E, int N, int D, int blk)
{
    const int lane   = threadIdx.x & 31;
    const int warp   = (blk * FUSED_THREADS + threadIdx.x) >> 5;
    const int nwarps = (EDGE_BLOCKS * FUSED_THREADS) >> 5;
    const int vecD   = D >> 2;                        // D % 4 == 0

    float acc = 0.0f;

    int e  = warp;
    int pi = (e < E) ? par[e] : 0;
    int ci = (e < E) ? chi[e] : 0;

    while (e < E) {
        const int en = e + nwarps;
        // prefetch next indices before consuming the current rows
        int pn = (en < E) ? par[en] : 0;
        int cn = (en < E) ? chi[en] : 0;

        // defensive clamp (free vs 2KB row traffic)
        pi = min(max(pi, 0), N - 1);
        ci = min(max(ci, 0), N - 1);

        const float4* __restrict__ pp =
            reinterpret_cast<const float4*>(emb + (size_t)pi * D);
        const float4* __restrict__ pc =
            reinterpret_cast<const float4*>(emb + (size_t)ci * D);
        #pragma unroll
        for (int i = lane; i < vecD; i += 32) {
            float4 a = pp[i];
            float4 b = pc[i];
            float dx = a.x - b.x, dy = a.y - b.y;
            float dz = a.z - b.z, dw = a.w - b.w;
            acc += dx * dx + dy * dy + dz * dz + dw * dw;
        }

        e = en; pi = pn; ci = cn;
    }

    __shared__ float red[FUSED_THREADS];
    const int t = threadIdx.x;
    red[t] = acc;
    __syncthreads();
    for (int off = FUSED_THREADS / 2; off > 0; off >>= 1) {
        if (t < off) red[t] += red[t + off];
        __syncthreads();
    }
    if (t == 0) g_edge_part[blk] = red[0];
}

// ---------------------------------------------------------------------------
// Fused kernel: block-partitioned dispatch of the two independent phases.
// ---------------------------------------------------------------------------
__global__ void __launch_bounds__(FUSED_THREADS)
fused_partial_kernel(const float* __restrict__ logits,
                     const float* __restrict__ emb,
                     const int* __restrict__ par,
                     const int* __restrict__ chi,
                     int B, int N, int E, int D)
{
    const int nLse = B * LSE_SPLIT;
    if (blockIdx.x < nLse) {
        lse_phase(logits, N, blockIdx.x);
    } else {
        edge_phase(emb, par, chi, E, N, D, blockIdx.x - nLse);
    }
}

// ---------------------------------------------------------------------------
// Final combine. One block.
//  - thread t < B: merge the LSE_SPLIT partials of row t, compute CE term.
//  - all threads: strided sum of edge partials.
//  - block reduce -> out[0]. Fully deterministic.
// ---------------------------------------------------------------------------
__global__ void final_kernel(const float* __restrict__ logits,
                             const int* __restrict__ labels,
                             float* __restrict__ out,
                             int B, int N)
{
    const int t = threadIdx.x;
    float v = 0.0f;

    if (t < B) {
        float m = g_lse_m[t * LSE_SPLIT];
        float s = g_lse_s[t * LSE_SPLIT];
        #pragma unroll
        for (int p = 1; p < LSE_SPLIT; p++) {
            float m2 = g_lse_m[t * LSE_SPLIT + p];
            float s2 = g_lse_s[t * LSE_SPLIT + p];
            float M = fmaxf(m, m2);
            s = s * __expf(m - M) + s2 * __expf(m2 - M);
            m = M;
        }
        float lse = m + logf(s);
        int lab = min(max(labels[t], 0), N - 1);   // defensive clamp
        v = (lse - logits[(size_t)t * N + lab]) / (float)B;
    }

    float ep = 0.0f;
    for (int i = t; i < EDGE_BLOCKS; i += blockDim.x) ep += g_edge_part[i];
    v += HIER_W * ep;

    __shared__ float red[256];
    red[t] = v;
    __syncthreads();
    for (int off = 128; off > 0; off >>= 1) {
        if (t < off) red[t] += red[t + off];
        __syncthreads();
    }
    if (t == 0) out[0] = red[0];
}

// ---------------------------------------------------------------------------
extern "C" void kernel_launch(void* const* d_in, const int* in_sizes, int n_in,
                              void* d_out, int out_size)
{
    const float* logits = (const float*)d_in[0];
    const int*   labels = (const int*)d_in[1];
    const float* emb    = (const float*)d_in[2];
    const int*   par    = (const int*)d_in[3];
    const int*   chi    = (const int*)d_in[4];
    float*       out    = (float*)d_out;

    const int B = in_sizes[1];                // 128
    const int N = in_sizes[0] / B;            // 100000
    const int D = in_sizes[2] / N;            // 256
    const int E = in_sizes[3];                // 99999

    const int nBlocks = B * LSE_SPLIT + EDGE_BLOCKS;
    fused_partial_kernel<<<nBlocks, FUSED_THREADS>>>(logits, emb, par, chi,
                                                     B, N, E, D);
    final_kernel<<<1, 256>>>(logits, labels, out, B, N);
}

// round 9
// speedup vs baseline: 1.1309x; 1.1309x over previous
#include <cuda_runtime.h>
#include <cuda_bf16.h>
#include <math.h>
#include <float.h>

// HierarchyLoss: out = mean_b( lse(logits[b]) - logits[b,label[b]] )
//              + 0.1 * sum_e ||emb[parent[e]] - emb[child[e]]||^2
//
// Inputs (all index tensors are int32 — JAX default x64-disabled):
//  0: logits    float32 [B, N]   B=128, N=100000
//  1: labels    int32   [B]
//  2: label_emb float32 [N, D]   D=256
//  3: parent_idx int32  [E]      E=N-1
//  4: child_idx  int32  [E]
// Output: float32 scalar.
//
// Single persistent kernel: one wave of 1184 blocks (8/SM x 148 SM).
// Per block: warps 0-1 -> LSE partials, warps 2-7 -> edge partials.
// Last-arriving block (atomic ticket) does the deterministic final combine.
// Single-touch streams (logits, indices) use __ldcs so the 102MB emb table
// stays L2-resident for the random edge gathers.

#define G_BLOCKS   1184
#define THREADS    256
#define NWARPS     8
#define LSE_WPB    2                 // LSE warps per block
#define EDGE_WPB   6                 // edge warps per block
#define LSE_SPLIT  16
#define MAX_B      256
#define HIER_W     0.1f

#define N_EDGE_WARPS (G_BLOCKS * EDGE_WPB)     // 7104

// Scratch (allocation-free rule: __device__ globals)
__device__ float        g_lse_m[MAX_B * LSE_SPLIT];
__device__ float        g_lse_s[MAX_B * LSE_SPLIT];
__device__ float        g_edge_part[G_BLOCKS];
__device__ float        g_ce_logit[MAX_B];
__device__ unsigned int g_count = 0;           // auto-wrap ticket (replay-safe)

__global__ void __launch_bounds__(THREADS)
hierarchy_loss_kernel(const float* __restrict__ logits,
                      const int*   __restrict__ labels,
                      const float* __restrict__ emb,
                      const int*   __restrict__ par,
                      const int*   __restrict__ chi,
                      float* __restrict__ out,
                      int B, int N, int E, int D)
{
    const int t    = threadIdx.x;
    const int warp = t >> 5;
    const int lane = t & 31;
    const int blk  = blockIdx.x;

    // ---- label-logit prefetch (block 0): warm g_ce_logit early -----------
    if (blk == 0 && t < B) {
        int lab = min(max(labels[t], 0), N - 1);
        g_ce_logit[t] = logits[(size_t)t * N + lab];
    }

    float edge_acc = 0.0f;

    if (warp < LSE_WPB) {
        // ================= LSE phase: one warp per (row, part) task =======
        const int task  = blk * LSE_WPB + warp;      // 0 .. 2367
        const int tasks = B * LSE_SPLIT;             // 2048
        if (task < tasks) {
            const int row  = task / LSE_SPLIT;
            const int part = task % LSE_SPLIT;
            const int vecN = N >> 2;                 // N % 4 == 0
            const int chunk = (vecN + LSE_SPLIT - 1) / LSE_SPLIT;
            const int c0 = part * chunk;
            const int c1 = min(c0 + chunk, vecN);

            const float4* __restrict__ p =
                reinterpret_cast<const float4*>(logits + (size_t)row * N);

            float m = -FLT_MAX, s = 0.0f;
            for (int i = c0 + lane; i < c1; i += 32) {
                float4 v = __ldcs(p + i);            // streaming: read-once
                float mv = fmaxf(fmaxf(v.x, v.y), fmaxf(v.z, v.w));
                if (mv > m) { s *= __expf(m - mv); m = mv; }
                s += __expf(v.x - m) + __expf(v.y - m) +
                     __expf(v.z - m) + __expf(v.w - m);
            }
            // warp-level (m,s) merge — fixed butterfly order, deterministic
            #pragma unroll
            for (int off = 16; off > 0; off >>= 1) {
                float m2 = __shfl_xor_sync(0xffffffffu, m, off);
                float s2 = __shfl_xor_sync(0xffffffffu, s, off);
                float M  = fmaxf(m, m2);
                s = s * __expf(m - M) + s2 * __expf(m2 - M);
                m = M;
            }
            if (lane == 0) { g_lse_m[task] = m; g_lse_s[task] = s; }
        }
    } else {
        // ================= Edge phase: warp-strided edges =================
        const int ew = blk * EDGE_WPB + (warp - LSE_WPB);  // 0 .. 7103

        int e  = ew;
        int pi = (e < E) ? __ldcs(par + e) : 0;
        int ci = (e < E) ? __ldcs(chi + e) : 0;

        if (D == 256) {
            // specialized: 64 float4/row, lane covers [lane] and [lane+32]
            while (e < E) {
                const int en = e + N_EDGE_WARPS;
                int pn = (en < E) ? __ldcs(par + en) : 0;  // prefetch next
                int cn = (en < E) ? __ldcs(chi + en) : 0;

                pi = min(max(pi, 0), N - 1);
                ci = min(max(ci, 0), N - 1);

                const float4* __restrict__ pp =
                    reinterpret_cast<const float4*>(emb + (size_t)pi * 256);
                const float4* __restrict__ pc =
                    reinterpret_cast<const float4*>(emb + (size_t)ci * 256);

                float4 a0 = pp[lane];
                float4 a1 = pp[lane + 32];
                float4 b0 = pc[lane];
                float4 b1 = pc[lane + 32];

                float dx = a0.x - b0.x, dy = a0.y - b0.y;
                float dz = a0.z - b0.z, dw = a0.w - b0.w;
                edge_acc += dx*dx + dy*dy + dz*dz + dw*dw;
                dx = a1.x - b1.x; dy = a1.y - b1.y;
                dz = a1.z - b1.z; dw = a1.w - b1.w;
                edge_acc += dx*dx + dy*dy + dz*dz + dw*dw;

                e = en; pi = pn; ci = cn;
            }
        } else {
            const int vecD = D >> 2;
            while (e < E) {
                const int en = e + N_EDGE_WARPS;
                int pn = (en < E) ? __ldcs(par + en) : 0;
                int cn = (en < E) ? __ldcs(chi + en) : 0;
                pi = min(max(pi, 0), N - 1);
                ci = min(max(ci, 0), N - 1);
                const float4* __restrict__ pp =
                    reinterpret_cast<const float4*>(emb + (size_t)pi * D);
                const float4* __restrict__ pc =
                    reinterpret_cast<const float4*>(emb + (size_t)ci * D);
                for (int i = lane; i < vecD; i += 32) {
                    float4 a = pp[i], b = pc[i];
                    float dx = a.x - b.x, dy = a.y - b.y;
                    float dz = a.z - b.z, dw = a.w - b.w;
                    edge_acc += dx*dx + dy*dy + dz*dz + dw*dw;
                }
                e = en; pi = pn; ci = cn;
            }
        }
    }

    // ---- per-block edge reduction (warp shfl + fixed-order across warps) -
    #pragma unroll
    for (int off = 16; off > 0; off >>= 1)
        edge_acc += __shfl_xor_sync(0xffffffffu, edge_acc, off);

    __shared__ float s_warp[NWARPS];
    if (lane == 0) s_warp[warp] = edge_acc;
    __syncthreads();
    if (t == 0) {
        float bsum = 0.0f;
        #pragma unroll
        for (int w = LSE_WPB; w < NWARPS; w++) bsum += s_warp[w];
        g_edge_part[blk] = bsum;
    }

    // ---- completion ticket ----------------------------------------------
    __shared__ bool s_last;
    if (t == 0) {
        __threadfence();
        unsigned int ticket = atomicInc(&g_count, G_BLOCKS - 1); // wraps->0
        s_last = (ticket == G_BLOCKS - 1);
    }
    __syncthreads();
    if (!s_last) return;

    // ================= final combine (last block, deterministic) =========
    __threadfence();

    float v = 0.0f;
    if (t < B) {
        float m = g_lse_m[t * LSE_SPLIT];
        float s = g_lse_s[t * LSE_SPLIT];
        #pragma unroll
        for (int p = 1; p < LSE_SPLIT; p++) {
            float m2 = g_lse_m[t * LSE_SPLIT + p];
            float s2 = g_lse_s[t * LSE_SPLIT + p];
            float M  = fmaxf(m, m2);
            s = s * __expf(m - M) + s2 * __expf(m2 - M);
            m = M;
        }
        v = (m + logf(s) - g_ce_logit[t]) / (float)B;
    }

    float ep = 0.0f;
    for (int i = t; i < G_BLOCKS; i += THREADS) ep += g_edge_part[i];
    v += HIER_W * ep;

    __shared__ float red[THREADS];
    red[t] = v;
    __syncthreads();
    #pragma unroll
    for (int off = THREADS / 2; off > 0; off >>= 1) {
        if (t < off) red[t] += red[t + off];
        __syncthreads();
    }
    if (t == 0) out[0] = red[0];
}

// ---------------------------------------------------------------------------
extern "C" void kernel_launch(void* const* d_in, const int* in_sizes, int n_in,
                              void* d_out, int out_size)
{
    const float* logits = (const float*)d_in[0];
    const int*   labels = (const int*)d_in[1];
    const float* emb    = (const float*)d_in[2];
    const int*   par    = (const int*)d_in[3];
    const int*   chi    = (const int*)d_in[4];
    float*       out    = (float*)d_out;

    const int B = in_sizes[1];                // 128
    const int N = in_sizes[0] / B;            // 100000
    const int D = in_sizes[2] / N;            // 256
    const int E = in_sizes[3];                // 99999

    hierarchy_loss_kernel<<<G_BLOCKS, THREADS>>>(logits, labels, emb, par, chi,
                                                 out, B, N, E, D);
}